// round 7
// baseline (speedup 1.0000x reference)
#include <cuda_runtime.h>
#include <math.h>

#define NSMP   256000        // = 512 * 500
#define N1     512
#define N2     500
#define NBATCH 4
#define NFR    500
#define NBK    64
#define NFQ    128001
#define NCH    10
#define CHF    50

// ---------------- scratch ----------------
__device__ float2 g_u[2][N1 * N2];     // 4 MB working buffer
__device__ float  g_H[NBATCH][NFQ];
__device__ float  g_part[NCH][NBATCH][NBK];

// ---------------- helpers ----------------
__device__ __forceinline__ float2 c_add(float2 a, float2 b){ return make_float2(a.x+b.x, a.y+b.y); }
__device__ __forceinline__ float2 c_sub(float2 a, float2 b){ return make_float2(a.x-b.x, a.y-b.y); }
__device__ __forceinline__ float2 cxm(float2 a, float2 b){
    return make_float2(a.x*b.x - a.y*b.y, a.x*b.y + a.y*b.x);
}

// constant twiddle tables: (cos, sin) of +2*pi*j/20 and +2*pi*j/25
__constant__ float2 TW20[13] = {
    { 1.f, 0.f},
    { 0.95105651629515353f, 0.30901699437494740f},
    { 0.80901699437494745f, 0.58778525229247314f},
    { 0.58778525229247314f, 0.80901699437494745f},
    { 0.30901699437494740f, 0.95105651629515353f},
    { 0.f, 1.f},
    {-0.30901699437494740f, 0.95105651629515353f},
    {-0.58778525229247314f, 0.80901699437494745f},
    {-0.80901699437494745f, 0.58778525229247314f},
    {-0.95105651629515353f, 0.30901699437494740f},
    {-1.f, 0.f},
    {-0.95105651629515353f,-0.30901699437494740f},
    {-0.80901699437494745f,-0.58778525229247314f}
};
__constant__ float2 TW25[17] = {
    { 1.f, 0.f},
    { 0.96858316112863108f, 0.24868988716485479f},
    { 0.87630668004386358f, 0.48175367410171532f},
    { 0.72896862742141155f, 0.68454710592868862f},
    { 0.53582679497899666f, 0.84432792550201508f},
    { 0.30901699437494740f, 0.95105651629515353f},
    { 0.06279051952931337f, 0.99802672842827156f},
    {-0.18738131458572463f, 0.98228725072868872f},
    {-0.42577929156507266f, 0.90482705246601947f},
    {-0.63742398974868964f, 0.77051324277578925f},
    {-0.80901699437494745f, 0.58778525229247314f},
    {-0.92977648588825146f, 0.36812455268467797f},
    {-0.99211470131447788f, 0.12533323356430426f},
    {-0.99211470131447788f,-0.12533323356430426f},
    {-0.92977648588825146f,-0.36812455268467797f},
    {-0.80901699437494745f,-0.58778525229247314f},
    {-0.63742398974868964f,-0.77051324277578925f}
};

template<bool INV>
__device__ __forceinline__ float2 twc(float2 z, float2 w) {
    float wi = INV ? w.y : -w.y;
    return make_float2(z.x*w.x - z.y*wi, z.x*wi + z.y*w.x);
}

template<int R, bool INV>
__device__ __forceinline__ void butterfly(float2* v) {
    const float s = INV ? 1.f : -1.f;
    if constexpr (R == 4) {
        float2 t0 = c_add(v[0], v[2]), t1 = c_sub(v[0], v[2]);
        float2 t2 = c_add(v[1], v[3]), t3 = c_sub(v[1], v[3]);
        float2 it3 = make_float2(-s * t3.y, s * t3.x);
        v[0] = c_add(t0, t2); v[2] = c_sub(t0, t2);
        v[1] = c_add(t1, it3); v[3] = c_sub(t1, it3);
    } else if constexpr (R == 5) {
        const float c1 = 0.30901699437494742f, c2 = -0.80901699437494745f;
        const float s1 = 0.95105651629515357f, s2 =  0.58778525229247312f;
        float2 t1 = c_add(v[1], v[4]), t2 = c_add(v[2], v[3]);
        float2 t3 = c_sub(v[1], v[4]), t4 = c_sub(v[2], v[3]);
        float2 x0 = v[0];
        float2 m1 = make_float2(x0.x + c1*t1.x + c2*t2.x, x0.y + c1*t1.y + c2*t2.y);
        float2 m2 = make_float2(x0.x + c2*t1.x + c1*t2.x, x0.y + c2*t1.y + c1*t2.y);
        float2 u1 = make_float2(s1*t3.x + s2*t4.x, s1*t3.y + s2*t4.y);
        float2 u2 = make_float2(s2*t3.x - s1*t4.x, s2*t3.y - s1*t4.y);
        float2 iu1 = make_float2(-s*u1.y, s*u1.x);
        float2 iu2 = make_float2(-s*u2.y, s*u2.x);
        v[0] = make_float2(x0.x + t1.x + t2.x, x0.y + t1.y + t2.y);
        v[1] = c_add(m1, iu1); v[4] = c_sub(m1, iu1);
        v[2] = c_add(m2, iu2); v[3] = c_sub(m2, iu2);
    }
}

template<bool INV>
__device__ __forceinline__ void bfly8(float2* v) {
    float2 u0[4] = { v[0], v[2], v[4], v[6] };
    float2 u1[4] = { v[1], v[3], v[5], v[7] };
    butterfly<4, INV>(u0);
    butterfly<4, INV>(u1);
    const float h  = 0.70710678118654752f;
    const float si = INV ? 1.f : -1.f;
    float2 t0 = u1[0];
    float2 t1 = make_float2(h*(u1[1].x - si*u1[1].y), h*(si*u1[1].x + u1[1].y));
    float2 t2 = make_float2(-si*u1[2].y, si*u1[2].x);
    float2 t3 = make_float2(h*(-u1[3].x - si*u1[3].y), h*(si*u1[3].x - u1[3].y));
    v[0] = c_add(u0[0], t0); v[4] = c_sub(u0[0], t0);
    v[1] = c_add(u0[1], t1); v[5] = c_sub(u0[1], t1);
    v[2] = c_add(u0[2], t2); v[6] = c_sub(u0[2], t2);
    v[3] = c_add(u0[3], t3); v[7] = c_sub(u0[3], t3);
}

// natural-order DFT-20 in registers (4 subsets x DFT-5, twiddle, DFT-4 across)
template<bool INV>
__device__ __forceinline__ void dft20(float2* v) {
    float2 u[20];
#pragma unroll
    for (int b = 0; b < 4; b++) {
        float2 y[5] = { v[b], v[b+4], v[b+8], v[b+12], v[b+16] };
        butterfly<5, INV>(y);
#pragma unroll
        for (int c = 0; c < 5; c++) u[b*5 + c] = y[c];
    }
#pragma unroll
    for (int b = 1; b < 4; b++)
#pragma unroll
        for (int c = 1; c < 5; c++)
            u[b*5 + c] = twc<INV>(u[b*5 + c], TW20[b*c]);
#pragma unroll
    for (int c = 0; c < 5; c++) {
        float2 y[4] = { u[c], u[5+c], u[10+c], u[15+c] };
        butterfly<4, INV>(y);
#pragma unroll
        for (int d = 0; d < 4; d++) v[c + 5*d] = y[d];
    }
}

// natural-order DFT-25 in registers (5 x DFT-5, twiddle, 5 x DFT-5)
template<bool INV>
__device__ __forceinline__ void dft25(float2* v) {
    float2 u[25];
#pragma unroll
    for (int b = 0; b < 5; b++) {
        float2 y[5] = { v[b], v[b+5], v[b+10], v[b+15], v[b+20] };
        butterfly<5, INV>(y);
#pragma unroll
        for (int c = 0; c < 5; c++) u[b*5 + c] = y[c];
    }
#pragma unroll
    for (int b = 1; b < 5; b++)
#pragma unroll
        for (int c = 1; c < 5; c++)
            u[b*5 + c] = twc<INV>(u[b*5 + c], TW25[b*c]);
#pragma unroll
    for (int c = 0; c < 5; c++) {
        float2 y[5] = { u[c], u[5+c], u[10+c], u[15+c], u[20+c] };
        butterfly<5, INV>(y);
#pragma unroll
        for (int d = 0; d < 5; d++) v[c + 5*d] = y[d];
    }
}

// multiply a[k] by w^k, k in [0,K), w = e^{i th}; 4-sincos hybrid, optional base factor
template<int K>
__device__ __forceinline__ void powmul(float2* a, float th, float2 base) {
    float sn, cs;
    __sincosf(th, &sn, &cs);
    float2 q1 = make_float2(cs, sn);
    float2 q2 = cxm(q1, q1), q3 = cxm(q2, q1), q4 = cxm(q2, q2);
    float2 Q[5] = { make_float2(1.f,0.f), q1, q2, q3, q4 };
    float2 P[5];
    P[0] = base;
#pragma unroll
    for (int A = 1; A < (K + 4) / 5; A++) {
        __sincosf((float)(5*A)*th, &sn, &cs);
        P[A] = cxm(base, make_float2(cs, sn));
    }
#pragma unroll
    for (int A = 0; A < (K + 4) / 5; A++)
#pragma unroll
        for (int b = 0; b < 5; b++) {
            int k = A*5 + b;
            if (k < K) a[k] = cxm(a[k], cxm(P[A], Q[b]));
        }
}

// one sincosf + power chain: multiply v[1..7] by w^r
__device__ __forceinline__ void tw8(float base, float2* v) {
    float sn, cs; __sincosf(base, &sn, &cs);
    float2 w1 = make_float2(cs, sn);
    float2 w2 = cxm(w1, w1);
    float2 w3 = cxm(w2, w1);
    float2 w4 = cxm(w2, w2);
    float2 w5 = cxm(w4, w1);
    float2 w6 = cxm(w3, w3);
    float2 w7 = cxm(w3, w4);
    v[1] = cxm(v[1], w1); v[2] = cxm(v[2], w2); v[3] = cxm(v[3], w3);
    v[4] = cxm(v[4], w4); v[5] = cxm(v[5], w5); v[6] = cxm(v[6], w6);
    v[7] = cxm(v[7], w7);
}

// ---------------- partial mean-magnitude (closed-form frame weights) ----------------
__global__ void k_mm_part(const float* __restrict__ mag) {
    int c = blockIdx.x, b = blockIdx.y;
    int t = threadIdx.x;    // 64
    __shared__ float sw[CHF];
    if (t < CHF) {
        int f = c*CHF + t;
        const double s = 499.0/255999.0;
        long long a1 = ((long long)f*255999LL + 498LL)/499LL;
        long long b1 = ((long long)(f+1)*255999LL + 498LL)/499LL - 1LL;
        if (b1 > 255999LL) b1 = 255999LL;
        double cnt1 = (double)(b1 - a1 + 1);
        double si1  = 0.5*(double)(a1 + b1)*cnt1;
        double sum  = cnt1*(double)(1 + f) - s*si1;
        if (f >= 1) {
            long long a2 = ((long long)(f-1)*255999LL + 498LL)/499LL;
            long long b2 = a1 - 1LL;
            if (b2 >= a2) {
                double cnt2 = (double)(b2 - a2 + 1);
                double si2  = 0.5*(double)(a2 + b2)*cnt2;
                sum += s*si2 - (double)(f-1)*cnt2;
            }
        }
        sw[t] = (float)(sum/256000.0);
    }
    __syncthreads();
    float acc = 0.f;
    const float* mp = mag + (b*NFR + c*CHF)*NBK + t;
#pragma unroll 10
    for (int f = 0; f < CHF; f++) acc += sw[f]*mp[f*NBK];
    g_part[c][b][t] = acc;
}

// ---------------- filter response H[b][f] ----------------
__global__ void __launch_bounds__(128) k_filter_H() {
    __shared__ float smm[NBATCH*NBK];
    int t = threadIdx.x;
    for (int i = t; i < NBATCH*NBK; i += 128) {
        float a = 0.f;
        const float* p = (const float*)g_part;
#pragma unroll
        for (int c = 0; c < NCH; c++) a += p[c*256 + i];
        smm[i] = a;
    }
    __syncthreads();

    int f = blockIdx.x*128 + t;
    if (f >= NFQ) return;

    const float la = 2.99573227355399f;                 // log(20)
    const float d  = (__logf(11025.0f) - la)/63.f;
    float freq = (float)f * (22050.0f/256000.0f);
    float xp = __logf(freq + 1e-7f) - la;

    float te = __expf(-2.f*xp*xp);
    float to = te * __expf(4.f*d*xp - 2.f*d*d);
    float Re = __expf(8.f*d*xp - 8.f*d*d);
    float Ro = Re * __expf(-8.f*d*d);
    const float g4 = __expf(-16.f*d*d);

    float sum = 0.f, a0 = 0.f, a1 = 0.f, a2 = 0.f, a3 = 0.f;
#pragma unroll
    for (int k = 0; k < 64; k += 2) {
        sum += te + to;
        a0 += te*smm[k]       + to*smm[k+1];
        a1 += te*smm[64+k]    + to*smm[65+k];
        a2 += te*smm[128+k]   + to*smm[129+k];
        a3 += te*smm[192+k]   + to*smm[193+k];
        te *= Re; Re *= g4;
        to *= Ro; Ro *= g4;
    }
    float inv = 1.f/(sum + 1e-7f);
    g_H[0][f] = a0*inv; g_H[1][f] = a1*inv;
    g_H[2][f] = a2*inv; g_H[3][f] = a3*inv;
}

// ---------------- pass 1: FFT-512 per column + cross twiddle (8 cols/block) ----------------
__global__ void __launch_bounds__(512) k_p1f(const float* __restrict__ noise) {
    __shared__ float2 sm[8][516];
    int tid = threadIdx.x;
    int c = tid & 7, j = tid >> 3;          // j in [0,64)
    int n2 = blockIdx.x*8 + c;
    bool val = (n2 < N2);
    int s = blockIdx.y;
    const float* n0r = noise + 2*s*NSMP;
    const float* n1r = noise + (2*s+1)*NSMP;

    float2 v[8];
    if (val) {
#pragma unroll
        for (int r = 0; r < 8; r++) {
            int idx = (j + 64*r)*N2 + n2;
            v[r] = make_float2(n0r[idx], n1r[idx]);
        }
    } else {
#pragma unroll
        for (int r = 0; r < 8; r++) v[r] = make_float2(0.f, 0.f);
    }
    bfly8<false>(v);
#pragma unroll
    for (int r = 0; r < 8; r++) sm[c][j*8 + r] = v[r];
    __syncthreads();
#pragma unroll
    for (int r = 0; r < 8; r++) v[r] = sm[c][j + 64*r];
    __syncthreads();
    {
        int m = j & 7;
        tw8(-6.2831853071795864f/64.f * (float)m, v);
        bfly8<false>(v);
        int db = (j >> 3)*64 + m;
#pragma unroll
        for (int r = 0; r < 8; r++) sm[c][db + 8*r] = v[r];
    }
    __syncthreads();
#pragma unroll
    for (int r = 0; r < 8; r++) v[r] = sm[c][j + 64*r];
    {
        tw8(-6.2831853071795864f/512.f * (float)j, v);
        bfly8<false>(v);
        if (val) {
            float cb = -6.2831853071795864f/256000.f * (float)n2;
            float snj, csj; __sincosf(cb*(float)j, &snj, &csj);
            float snW, csW; __sincosf(cb*64.f, &snW, &csW);
            float2 wk = make_float2(csj, snj);
            float2 W  = make_float2(csW, snW);
            float2* u = g_u[s];
#pragma unroll
            for (int r = 0; r < 8; r++) {
                int k1 = j + 64*r;
                u[k1*N2 + n2] = cxm(v[r], wk);
                wk = cxm(wk, W);
            }
        }
    }
}

// ---------------- fused middle: register FFT-500 (20x25) + filter + inverse ----------------
// One 64-thread block = one conjugate pair of rows {p, 512-p}; warp = one row.
__global__ void __launch_bounds__(64) k_pMid() {
    __shared__ float2 sh[2][544];     // [k1*27+n2] layout fwd, [n2*21+k1] layout inv
    int tid = threadIdx.x;
    int half = tid >> 5;
    int lane = tid & 31;
    int p = blockIdx.x;               // 0..255
    int s = blockIdx.y;
    int myrow = half ? ((p == 0) ? 256 : 512 - p) : p;
    float2* M = sh[half];
    const float TPI = 6.2831853071795864f;
    const float2 ONE = make_float2(1.f, 0.f);

    // F1: lane = n2 — DFT-20 in regs, twiddle W500^{-n2 k1}, transpose to smem
    if (lane < 25) {
        const float2* src = g_u[s] + myrow*N2;
        float2 a[20];
#pragma unroll
        for (int n1 = 0; n1 < 20; n1++) a[n1] = src[25*n1 + lane];
        dft20<false>(a);
        powmul<20>(a, -TPI/500.f * (float)lane, ONE);
#pragma unroll
        for (int k1 = 0; k1 < 20; k1++) M[k1*27 + lane] = a[k1];
    }
    __syncwarp();

    // F2: lane = k1 — DFT-25 in regs; spectrum S[k2] = Z[k1 + 20 k2]; exchange copy
    float2 S[25];
    if (lane < 20) {
#pragma unroll
        for (int n2 = 0; n2 < 25; n2++) S[n2] = M[lane*27 + n2];
        dft25<false>(S);
#pragma unroll
        for (int k2 = 0; k2 < 25; k2++) M[lane*27 + k2] = S[k2];
    }
    __syncthreads();

    // F3: spectral filter (pair (k1,k2) <-> (19-k1, 24-k2)) + iDFT-25 + twiddle, all in regs
    if (lane < 20) {
        const float* H0 = g_H[2*s];
        const float* H1 = g_H[2*s+1];
        const float2* pairbuf = (p == 0) ? M : sh[1-half];
        bool row0 = (p == 0) && (half == 0);
#pragma unroll
        for (int k2 = 0; k2 < 25; k2++) {
            int kk = lane + 20*k2;
            float2 zk = S[k2];
            float2 zn;
            if (row0) {
                int j = kk ? 500 - kk : 0;
                zn = M[(j % 20)*27 + (j / 20)];
            } else {
                zn = pairbuf[(19 - lane)*27 + (24 - k2)];
            }
            int k  = myrow + (kk << 9);
            int kh = (k <= 128000) ? k : 256000 - k;
            float h0 = H0[kh], h1 = H1[kh];
            float X0r = 0.5f*(zk.x + zn.x), X0i = 0.5f*(zk.y - zn.y);
            float X1r = 0.5f*(zk.y + zn.y), X1i = -0.5f*(zk.x - zn.x);
            S[k2] = make_float2(h0*X0r - h1*X1i, h0*X0i + h1*X1r);
        }
        dft25<true>(S);                              // iFFT over k2, no transpose needed
        powmul<25>(S, TPI/500.f * (float)lane, ONE); // W500^{+n2 k1}
    }
    __syncthreads();    // pair must finish reading exchange before overwrite
    if (lane < 20) {
#pragma unroll
        for (int n2 = 0; n2 < 25; n2++) M[n2*21 + lane] = S[n2];
    }
    __syncwarp();

    // F5: lane = n2 — iDFT-20 in regs, cross twiddle, store
    if (lane < 25) {
        float2 x[20];
#pragma unroll
        for (int k1 = 0; k1 < 20; k1++) x[k1] = M[lane*21 + k1];
        dft20<true>(x);
        float cb = TPI/256000.f * (float)myrow;
        float sn, cs; __sincosf(cb*(float)lane, &sn, &cs);
        powmul<20>(x, cb*25.f, make_float2(cs, sn));  // base w^{n2} * (w^{25})^{n1}
        float2* dst = g_u[s] + myrow*N2;
#pragma unroll
        for (int n1 = 0; n1 < 20; n1++) dst[25*n1 + lane] = x[n1];
    }
}

// ---------------- pass B: iFFT-512 per column + scale + unpack (8 cols/block) ----------------
__global__ void __launch_bounds__(512) k_pBi(float* __restrict__ out) {
    __shared__ float2 sm[8][516];
    int tid = threadIdx.x;
    int c = tid & 7, j = tid >> 3;
    int n2 = blockIdx.x*8 + c;
    bool val = (n2 < N2);
    int s = blockIdx.y;
    const float2* u = g_u[s];

    float2 v[8];
    if (val) {
#pragma unroll
        for (int r = 0; r < 8; r++) v[r] = u[(j + 64*r)*N2 + n2];
    } else {
#pragma unroll
        for (int r = 0; r < 8; r++) v[r] = make_float2(0.f, 0.f);
    }
    bfly8<true>(v);
#pragma unroll
    for (int r = 0; r < 8; r++) sm[c][j*8 + r] = v[r];
    __syncthreads();
#pragma unroll
    for (int r = 0; r < 8; r++) v[r] = sm[c][j + 64*r];
    __syncthreads();
    {
        int m = j & 7;
        tw8(6.2831853071795864f/64.f * (float)m, v);
        bfly8<true>(v);
        int db = (j >> 3)*64 + m;
#pragma unroll
        for (int r = 0; r < 8; r++) sm[c][db + 8*r] = v[r];
    }
    __syncthreads();
#pragma unroll
    for (int r = 0; r < 8; r++) v[r] = sm[c][j + 64*r];
    {
        tw8(6.2831853071795864f/512.f * (float)j, v);
        bfly8<true>(v);
        if (val) {
            const float sc = 1.f/256000.f;
            float* o0 = out + 2*s*NSMP;
            float* o1 = out + (2*s+1)*NSMP;
#pragma unroll
            for (int r = 0; r < 8; r++) {
                int idx = (j + 64*r)*N2 + n2;
                o0[idx] = v[r].x * sc;
                o1[idx] = v[r].y * sc;
            }
        }
    }
}

// ---------------- launch ----------------
extern "C" void kernel_launch(void* const* d_in, const int* in_sizes, int n_in,
                              void* d_out, int out_size) {
    const float* mag;
    const float* noise;
    if (in_sizes[0] == NBATCH*NFR*NBK) { mag = (const float*)d_in[0]; noise = (const float*)d_in[1]; }
    else                               { mag = (const float*)d_in[1]; noise = (const float*)d_in[0]; }
    float* out = (float*)d_out;

    k_mm_part<<<dim3(NCH, NBATCH), 64>>>(mag);
    k_filter_H<<<(NFQ + 127)/128, 128>>>();
    k_p1f<<<dim3(63, 2), 512>>>(noise);
    k_pMid<<<dim3(256, 2), 64>>>();
    k_pBi<<<dim3(63, 2), 512>>>(out);
}